// round 6
// baseline (speedup 1.0000x reference)
#include <cuda_runtime.h>

#define NTHREADS 512
#define NWARPS   16
#define RB       16     // rows per warp batch

typedef unsigned long long u64;

// ---- packed f32x2 helpers (FFMA2 path, PTX-only per SASS_QUICKREF) ----
__device__ __forceinline__ u64 fma2(u64 a, u64 b, u64 c) {
    u64 d;
    asm("fma.rn.f32x2 %0, %1, %2, %3;" : "=l"(d) : "l"(a), "l"(b), "l"(c));
    return d;
}
__device__ __forceinline__ float hsum2(u64 a) {
    float lo, hi;
    asm("mov.b64 {%0,%1}, %2;" : "=f"(lo), "=f"(hi) : "l"(a));
    return lo + hi;
}

// ---- shared memory layout (float offsets) ----
// W1/W2 row stride 132 (== 4 mod 32): the 8 ug-groups of a hidden weight
// LDS.128 land on distinct bank quads -> 1 wavefront per instruction.
#define OFF_W1  0
#define SZ_W1   (64 * 132)
#define OFF_W2  (OFF_W1 + SZ_W1)
#define SZ_W2   (32 * 132)
#define OFF_WF  (OFF_W2 + SZ_W2)
#define SZ_WF   (128 * 68)
#define OFF_B1  (OFF_WF + SZ_WF)
#define OFF_B2  (OFF_B1 + 64)
#define OFF_BF  (OFF_B2 + 32)
#define OFF_O   (OFF_BF + 128)
#define OSTRIDE 72                    // (8*rg+ug) mod 32 distinct -> 1wf STS.32
#define SZ_O    (NWARPS * RB * OSTRIDE)
#define SMEM_FLOATS (OFF_O + SZ_O)    // ~160 KB

// Final layer on 8 rows: out[r][dd] = bf[dd] + sum_u o[r][u] * Wf[dd][u]
// Lane handles dd = lane + 32k, k=0..3, all 8 rows (acc in regs, pack over u).
template<int UC>
__device__ __forceinline__ void final8(const float* __restrict__ sO8,
                                       const float* __restrict__ sWf,
                                       const float bfr[4],
                                       float* __restrict__ out,
                                       long row0, int lane)
{
    u64 acc[8][4];
    #pragma unroll
    for (int r = 0; r < 8; r++)
        #pragma unroll
        for (int k = 0; k < 4; k++) acc[r][k] = 0ull;

    #pragma unroll
    for (int uc = 0; uc < UC; uc++) {
        ulonglong2 wf[4];
        #pragma unroll
        for (int k = 0; k < 4; k++)
            wf[k] = *reinterpret_cast<const ulonglong2*>(sWf + (lane + 32 * k) * 68 + uc * 4);
        #pragma unroll
        for (int r = 0; r < 8; r++) {
            ulonglong2 o2 = *reinterpret_cast<const ulonglong2*>(sO8 + r * OSTRIDE + uc * 4);
            #pragma unroll
            for (int k = 0; k < 4; k++) {
                acc[r][k] = fma2(o2.x, wf[k].x, acc[r][k]);
                acc[r][k] = fma2(o2.y, wf[k].y, acc[r][k]);
            }
        }
    }
    #pragma unroll
    for (int r = 0; r < 8; r++) {
        float* orow = out + (row0 + r) * 128;
        #pragma unroll
        for (int k = 0; k < 4; k++)
            orow[lane + 32 * k] = hsum2(acc[r][k]) + bfr[k];
    }
}

__global__ void __launch_bounds__(NTHREADS, 1)
dynlayer_kernel(const float* __restrict__ X,  const float* __restrict__ W1,
                const float* __restrict__ b1, const float* __restrict__ W2,
                const float* __restrict__ b2, const float* __restrict__ Wf,
                const float* __restrict__ bf, float* __restrict__ out, int nrows)
{
    extern __shared__ float sm[];
    const int tid = threadIdx.x;

    // Stage weights once per CTA
    for (int i = tid; i < 64 * 128; i += NTHREADS) sm[OFF_W1 + (i >> 7) * 132 + (i & 127)] = W1[i];
    for (int i = tid; i < 32 * 128; i += NTHREADS) sm[OFF_W2 + (i >> 7) * 132 + (i & 127)] = W2[i];
    for (int i = tid; i < 128 * 64; i += NTHREADS) sm[OFF_WF + (i >> 6) * 68  + (i & 63)]  = Wf[i];
    if (tid < 64)  sm[OFF_B1 + tid] = b1[tid];
    if (tid < 32)  sm[OFF_B2 + tid] = b2[tid];
    if (tid < 128) sm[OFF_BF + tid] = bf[tid];
    __syncthreads();

    const int warp = tid >> 5, lane = tid & 31;
    const int ug = lane & 7, rg = lane >> 3;
    float* sOw = sm + OFF_O + warp * (RB * OSTRIDE);
    const float* sW1 = sm + OFF_W1;
    const float* sW2 = sm + OFF_W2;
    const float* sWf = sm + OFF_WF;

    float bfr[4];
    #pragma unroll
    for (int k = 0; k < 4; k++) bfr[k] = sm[OFF_BF + lane + 32 * k];
    float b2r[4];
    #pragma unroll
    for (int i = 0; i < 4; i++) b2r[i] = sm[OFF_B2 + ug + 8 * i];
    const float b1lo = sm[OFF_B1 + lane];
    const float b1hi = sm[OFF_B1 + lane + 32];
    const float b2lo = sm[OFF_B2 + lane];

    const int nb = nrows / RB;
    const int stride = gridDim.x * NWARPS;

    for (int b = (int)blockIdx.x * NWARPS + warp; b < nb; b += stride) {
        const long r0 = (long)b * RB;

        // ---- mask pre-pass: per-row sum|x| (also warms L1 with the x tile) ----
        unsigned m = 0;
        #pragma unroll
        for (int h = 0; h < 2; h++) {
            const float4* X4 = reinterpret_cast<const float4*>(X) + (r0 + h * 8) * 32 + lane;
            float s[8];
            #pragma unroll
            for (int r = 0; r < 8; r++) {
                float4 g = X4[r * 32];
                s[r] = fabsf(g.x) + fabsf(g.y) + fabsf(g.z) + fabsf(g.w);
            }
            #pragma unroll
            for (int off = 16; off > 0; off >>= 1)
                #pragma unroll
                for (int r = 0; r < 8; r++)
                    s[r] += __shfl_xor_sync(0xffffffffu, s[r], off);
            #pragma unroll
            for (int r = 0; r < 8; r++)
                if (s[r] > 128.0f) m |= (1u << (h * 8 + r));   // sum > 128 <=> mean > 1
        }

        if (m == 0u) {
            // ---- fast path: all 16 rows branch2. Lane computes units ug+8i (i<4)
            //      for rows rg+4j (j<4); x straight from global (L1-resident). ----
            u64 acc[4][4];
            #pragma unroll
            for (int i = 0; i < 4; i++)
                #pragma unroll
                for (int j = 0; j < 4; j++) acc[i][j] = 0ull;

            const float* wbase = sW2 + ug * 132;
            const float* xbase = X + (r0 + rg) * 128;

            #pragma unroll 8
            for (int dc = 0; dc < 32; dc++) {
                ulonglong2 xa[4];
                #pragma unroll
                for (int j = 0; j < 4; j++)
                    xa[j] = *reinterpret_cast<const ulonglong2*>(xbase + j * (4 * 128) + dc * 4);
                ulonglong2 wv[4];
                #pragma unroll
                for (int i = 0; i < 4; i++)
                    wv[i] = *reinterpret_cast<const ulonglong2*>(wbase + i * (8 * 132) + dc * 4);
                #pragma unroll
                for (int i = 0; i < 4; i++)
                    #pragma unroll
                    for (int j = 0; j < 4; j++) {
                        acc[i][j] = fma2(xa[j].x, wv[i].x, acc[i][j]);
                        acc[i][j] = fma2(xa[j].y, wv[i].y, acc[i][j]);
                    }
            }

            // relu + bias, scatter to sOw (conflict-free STS.32, stride 72)
            #pragma unroll
            for (int j = 0; j < 4; j++)
                #pragma unroll
                for (int i = 0; i < 4; i++) {
                    float o = hsum2(acc[i][j]) + b2r[i];
                    sOw[(rg + 4 * j) * OSTRIDE + ug + 8 * i] = fmaxf(o, 0.0f);
                }
            __syncwarp();

            final8<8>(sOw,               sWf, bfr, out, r0,     lane);
            final8<8>(sOw + 8 * OSTRIDE, sWf, bfr, out, r0 + 8, lane);
        } else {
            // ---- rare mixed path: per-row, lane = unit, 64-wide padded o ----
            #pragma unroll 1
            for (int r = 0; r < RB; r++) {
                const bool mk = (m >> r) & 1u;
                const float* W  = mk ? sW1 : sW2;
                const float* xr = X + (r0 + r) * 128;
                const float* w0 = W + lane * 132;
                const float* w1 = sW1 + (lane + 32) * 132;
                u64 aA = 0ull, aB = 0ull, cA = 0ull, cB = 0ull;
                #pragma unroll 8
                for (int dc = 0; dc < 32; dc++) {
                    ulonglong2 x2 = *reinterpret_cast<const ulonglong2*>(xr + dc * 4);
                    ulonglong2 wv = *reinterpret_cast<const ulonglong2*>(w0 + dc * 4);
                    aA = fma2(x2.x, wv.x, aA);
                    aB = fma2(x2.y, wv.y, aB);
                    if (mk) {
                        ulonglong2 wb = *reinterpret_cast<const ulonglong2*>(w1 + dc * 4);
                        cA = fma2(x2.x, wb.x, cA);
                        cB = fma2(x2.y, wb.y, cB);
                    }
                }
                const float bb = mk ? b1lo : b2lo;
                sOw[r * OSTRIDE + lane] = fmaxf(hsum2(aA) + hsum2(aB) + bb, 0.0f);
                float ohi = 0.0f;
                if (mk) ohi = fmaxf(hsum2(cA) + hsum2(cB) + b1hi, 0.0f);
                sOw[r * OSTRIDE + lane + 32] = ohi;
            }
            __syncwarp();

            final8<16>(sOw,               sWf, bfr, out, r0,     lane);
            final8<16>(sOw + 8 * OSTRIDE, sWf, bfr, out, r0 + 8, lane);
        }
        __syncwarp();
    }
}

extern "C" void kernel_launch(void* const* d_in, const int* in_sizes, int n_in,
                              void* d_out, int out_size)
{
    const float* X  = (const float*)d_in[0];
    const float* W1 = (const float*)d_in[1];
    const float* b1 = (const float*)d_in[2];
    const float* W2 = (const float*)d_in[3];
    const float* b2 = (const float*)d_in[4];
    const float* Wf = (const float*)d_in[5];
    const float* bf = (const float*)d_in[6];
    float* out = (float*)d_out;

    const int nrows = in_sizes[0] / 128;
    const size_t smem = SMEM_FLOATS * sizeof(float);

    cudaFuncSetAttribute(dynlayer_kernel,
                         cudaFuncAttributeMaxDynamicSharedMemorySize, (int)smem);

    int nsm = 148;
    cudaDeviceGetAttribute(&nsm, cudaDevAttrMultiProcessorCount, 0);

    dynlayer_kernel<<<nsm, NTHREADS, smem>>>(X, W1, b1, W2, b2, Wf, bf, out, nrows);
}

// round 9
// speedup vs baseline: 1.8672x; 1.8672x over previous
#include <cuda_runtime.h>
#include <cuda_bf16.h>
#include <cstdint>

#define NTHREADS 256

// ---- smem layout (bf16-element offsets) ----
#define XSTR  136                      // 128 + 8 pad -> 17 16B-units (odd, conflict-free)
#define ASTR  72                       // 64 + 8 pad  -> 9 16B-units
#define O_W2H 0
#define O_W2L (O_W2H + 32 * XSTR)
#define O_WFH (O_W2L + 32 * XSTR)
#define O_WFL (O_WFH + 128 * ASTR)
#define O_X   (O_WFL + 128 * ASTR)
#define XW    (16 * XSTR)              // per-warp x buffer (one of hi/lo)
#define O_A2  (O_X + 8 * 2 * XW)
#define AW    (16 * ASTR)
#define SM_UNITS (O_A2 + 8 * 2 * AW)
#define O_BIAS   (SM_UNITS * 2)        // byte offset, 4B-aligned
#define SM_BYTES (O_BIAS + 4 * (32 + 128))

typedef unsigned u32;

static __device__ __forceinline__ u32 s2u(const void* p) {
    u32 a;
    asm("{ .reg .u64 t; cvta.to.shared.u64 t, %1; cvt.u32.u64 %0, t; }" : "=r"(a) : "l"(p));
    return a;
}
static __device__ __forceinline__ void bfsplit(float v, __nv_bfloat16& h, __nv_bfloat16& l) {
    h = __float2bfloat16(v);
    l = __float2bfloat16(v - __bfloat162float(h));
}
static __device__ __forceinline__ u32 pk(__nv_bfloat16 a, __nv_bfloat16 b) {
    return (u32)__bfloat16_as_ushort(a) | ((u32)__bfloat16_as_ushort(b) << 16);
}

static __device__ __forceinline__ void ldmx4(u32 a[4], u32 addr) {
    asm volatile("ldmatrix.sync.aligned.m8n8.x4.shared.b16 {%0,%1,%2,%3}, [%4];"
                 : "=r"(a[0]), "=r"(a[1]), "=r"(a[2]), "=r"(a[3]) : "r"(addr));
}
// B operand: weights stored [n][k] row-major; NON-transposed ldmatrix gives the
// row.col B fragment directly (pair contiguous along k, n = lane/4).
static __device__ __forceinline__ void ldmx2(u32& b0, u32& b1, u32 addr) {
    asm volatile("ldmatrix.sync.aligned.m8n8.x2.shared.b16 {%0,%1}, [%2];"
                 : "=r"(b0), "=r"(b1) : "r"(addr));
}
static __device__ __forceinline__ void mmabf(float c[4], const u32 a[4], u32 b0, u32 b1) {
    asm volatile("mma.sync.aligned.m16n8k16.row.col.f32.bf16.bf16.f32 "
                 "{%0,%1,%2,%3}, {%4,%5,%6,%7}, {%8,%9}, {%0,%1,%2,%3};"
                 : "+f"(c[0]), "+f"(c[1]), "+f"(c[2]), "+f"(c[3])
                 : "r"(a[0]), "r"(a[1]), "r"(a[2]), "r"(a[3]), "r"(b0), "r"(b1));
}

__global__ void __launch_bounds__(NTHREADS, 1)
dynlayer_mma(const float* __restrict__ X,  const float* __restrict__ W1,
             const float* __restrict__ b1, const float* __restrict__ W2,
             const float* __restrict__ b2, const float* __restrict__ Wf,
             const float* __restrict__ bf, float* __restrict__ out, int nrows)
{
    extern __shared__ char smraw[];
    __nv_bfloat16* sh = (__nv_bfloat16*)smraw;
    float* b2s = (float*)(smraw + O_BIAS);
    float* bfs = b2s + 32;
    const u32 sb = s2u(smraw);
    const int tid = threadIdx.x, wid = tid >> 5, lane = tid & 31;

    // ---- stage weights: bf16 hi/lo, padded row-major ----
    for (int i = tid; i < 32 * 128; i += NTHREADS) {
        int u = i >> 7, k = i & 127; __nv_bfloat16 h, l; bfsplit(W2[i], h, l);
        sh[O_W2H + u * XSTR + k] = h; sh[O_W2L + u * XSTR + k] = l;
    }
    for (int i = tid; i < 128 * 64; i += NTHREADS) {
        int n = i >> 6, k = i & 63; __nv_bfloat16 h, l; bfsplit(Wf[i], h, l);
        sh[O_WFH + n * ASTR + k] = h; sh[O_WFL + n * ASTR + k] = l;
    }
    if (tid < 32)  b2s[tid] = b2[tid];
    if (tid < 128) bfs[tid] = bf[tid];
    __syncthreads();

    const int xh = O_X + wid * (2 * XW), xl = xh + XW;
    const int ah = O_A2 + wid * (2 * AW), al = ah + AW;
    const int ntiles = nrows >> 7;

    for (int t = blockIdx.x; t < ntiles; t += gridDim.x) {
        const long rw = ((long)t << 7) + wid * 16;   // this warp's 16 rows

        // ---- stage x rows (coalesced LDG.128), split bf16, per-row mask ----
        unsigned m = 0;
        const float4* Xp = reinterpret_cast<const float4*>(X) + rw * 32 + lane;
        #pragma unroll 4
        for (int i = 0; i < 16; i++) {
            float4 g = Xp[i * 32];
            __nv_bfloat16 h0,h1,h2,h3, l0,l1,l2,l3;
            bfsplit(g.x,h0,l0); bfsplit(g.y,h1,l1); bfsplit(g.z,h2,l2); bfsplit(g.w,h3,l3);
            int o = i * XSTR + lane * 4;
            *(uint2*)(sh + xh + o) = make_uint2(pk(h0,h1), pk(h2,h3));
            *(uint2*)(sh + xl + o) = make_uint2(pk(l0,l1), pk(l2,l3));
            float s = fabsf(g.x) + fabsf(g.y) + fabsf(g.z) + fabsf(g.w);
            #pragma unroll
            for (int off = 16; off > 0; off >>= 1) s += __shfl_xor_sync(0xffffffffu, s, off);
            if (s > 128.0f) m |= (1u << i);          // sum>128 <=> mean|x|>1
        }
        __syncwarp();

        // prefetch next tile's x into L2
        if (t + gridDim.x < ntiles) {
            const char* p = (const char*)(X + (rw + (long)gridDim.x * 128) * 128);
            asm volatile("prefetch.global.L2 [%0];" :: "l"(p + lane * 256));
        }

        // ---- GEMM1: o2 = x @ W2^T  (M=16, N=32, K=128; 3-term bf16 split) ----
        float acc1[4][4];
        #pragma unroll
        for (int nb = 0; nb < 4; nb++)
            #pragma unroll
            for (int j = 0; j < 4; j++) acc1[nb][j] = 0.0f;

        #pragma unroll
        for (int kb = 0; kb < 8; kb++) {
            const int acol = kb * 16 + ((lane >> 4) << 3);
            u32 aAddr = sb + (u32)(( (lane & 15) * XSTR + acol ) * 2);
            u32 ah4[4], al4[4];
            ldmx4(ah4, aAddr + xh * 2);
            ldmx4(al4, aAddr + xl * 2);
            const int bcol = kb * 16 + ((lane & 8) ? 8 : 0);
            #pragma unroll
            for (int nb = 0; nb < 4; nb++) {
                u32 bAddr = sb + (u32)(( (nb * 8 + (lane & 7)) * XSTR + bcol ) * 2);
                u32 bh0, bh1, bl0, bl1;
                ldmx2(bh0, bh1, bAddr + O_W2H * 2);
                ldmx2(bl0, bl1, bAddr + O_W2L * 2);
                mmabf(acc1[nb], ah4, bh0, bh1);
                mmabf(acc1[nb], ah4, bl0, bl1);
                mmabf(acc1[nb], al4, bh0, bh1);
            }
        }

        // ---- epilogue1: bias+relu, split to A2 (cols 0..31) ----
        {
            const int r = lane >> 2;
            #pragma unroll
            for (int nb = 0; nb < 4; nb++) {
                const int col = nb * 8 + (lane & 3) * 2;
                float ba = b2s[col], bb = b2s[col + 1];
                float v00 = fmaxf(acc1[nb][0] + ba, 0.0f), v01 = fmaxf(acc1[nb][1] + bb, 0.0f);
                float v10 = fmaxf(acc1[nb][2] + ba, 0.0f), v11 = fmaxf(acc1[nb][3] + bb, 0.0f);
                __nv_bfloat16 h0,l0,h1,l1;
                bfsplit(v00,h0,l0); bfsplit(v01,h1,l1);
                *(u32*)(sh + ah + r * ASTR + col) = pk(h0,h1);
                *(u32*)(sh + al + r * ASTR + col) = pk(l0,l1);
                bfsplit(v10,h0,l0); bfsplit(v11,h1,l1);
                *(u32*)(sh + ah + (r + 8) * ASTR + col) = pk(h0,h1);
                *(u32*)(sh + al + (r + 8) * ASTR + col) = pk(l0,l1);
            }
        }
        __syncwarp();
        if (m) {   // rare: patch masked rows with branch1 (o1, 64 units), zero-pad others
            for (int i = 0; i < 16; i++) {
                if ((m >> i) & 1u) {
                    const float* xg = X + (rw + i) * 128;   // exact fp32 x from global
                    for (int u = lane; u < 64; u += 32) {
                        const float* wrow = W1 + u * 128;
                        float s = 0.0f;
                        for (int k = 0; k < 128; k++) s = fmaf(xg[k], wrow[k], s);
                        s = fmaxf(s + b1[u], 0.0f);
                        __nv_bfloat16 h, l; bfsplit(s, h, l);
                        sh[ah + i * ASTR + u] = h;
                        sh[al + i * ASTR + u] = l;
                    }
                } else {
                    sh[ah + i * ASTR + 32 + lane] = __float2bfloat16(0.0f);
                    sh[al + i * ASTR + 32 + lane] = __float2bfloat16(0.0f);
                }
            }
            __syncwarp();
        }

        // ---- GEMM2: out = A2 @ Wf^T  (M=16, N=128, K=64 or 32) ----
        float acc2[16][4];
        #pragma unroll
        for (int nb = 0; nb < 16; nb++)
            #pragma unroll
            for (int j = 0; j < 4; j++) acc2[nb][j] = 0.0f;

        const int kmax = m ? 4 : 2;
        for (int kb = 0; kb < kmax; kb++) {
            const int acol = kb * 16 + ((lane >> 4) << 3);
            u32 aAddr = sb + (u32)(( (lane & 15) * ASTR + acol ) * 2);
            u32 ah4[4], al4[4];
            ldmx4(ah4, aAddr + ah * 2);
            ldmx4(al4, aAddr + al * 2);
            const int bcol = kb * 16 + ((lane & 8) ? 8 : 0);
            #pragma unroll
            for (int nb = 0; nb < 16; nb++) {
                u32 bAddr = sb + (u32)(( (nb * 8 + (lane & 7)) * ASTR + bcol ) * 2);
                u32 bh0, bh1, bl0, bl1;
                ldmx2(bh0, bh1, bAddr + O_WFH * 2);
                ldmx2(bl0, bl1, bAddr + O_WFL * 2);
                mmabf(acc2[nb], ah4, bh0, bh1);
                mmabf(acc2[nb], ah4, bl0, bl1);
                mmabf(acc2[nb], al4, bh0, bh1);
            }
        }

        // ---- epilogue2: + bf, store fp32 (float2 per row-block) ----
        {
            const long r1 = rw + (lane >> 2), r2 = r1 + 8;
            #pragma unroll
            for (int nb = 0; nb < 16; nb++) {
                const int col = nb * 8 + (lane & 3) * 2;
                float ba = bfs[col], bb = bfs[col + 1];
                *reinterpret_cast<float2*>(out + r1 * 128 + col) =
                    make_float2(acc2[nb][0] + ba, acc2[nb][1] + bb);
                *reinterpret_cast<float2*>(out + r2 * 128 + col) =
                    make_float2(acc2[nb][2] + ba, acc2[nb][3] + bb);
            }
        }
        __syncwarp();
    }
}

extern "C" void kernel_launch(void* const* d_in, const int* in_sizes, int n_in,
                              void* d_out, int out_size)
{
    const float* X  = (const float*)d_in[0];
    const float* W1 = (const float*)d_in[1];
    const float* b1 = (const float*)d_in[2];
    const float* W2 = (const float*)d_in[3];
    const float* b2 = (const float*)d_in[4];
    const float* Wf = (const float*)d_in[5];
    const float* bf = (const float*)d_in[6];
    float* out = (float*)d_out;

    const int nrows = in_sizes[0] / 128;

    cudaFuncSetAttribute(dynlayer_mma,
                         cudaFuncAttributeMaxDynamicSharedMemorySize, SM_BYTES);
    int nsm = 148;
    cudaDeviceGetAttribute(&nsm, cudaDevAttrMultiProcessorCount, 0);

    dynlayer_mma<<<nsm, NTHREADS, SM_BYTES>>>(X, W1, b1, W2, b2, Wf, bf, out, nrows);
}

// round 10
// speedup vs baseline: 3.0221x; 1.6185x over previous
#include <cuda_runtime.h>
#include <cuda_bf16.h>
#include <cstdint>

#define NTHREADS 256

// ---- smem: weights only (bf16-element offsets) ----
#define XSTR  136                      // W2 row stride: 272B = 68 words == 4 mod 32 -> conflict-free ldmatrix
#define ASTR  72                       // Wf row stride: 144B = 36 words == 4 mod 32
#define O_W2H 0
#define O_W2L (32 * XSTR)
#define O_WFH (2 * 32 * XSTR)
#define O_WFL (O_WFH + 128 * ASTR)
#define SM_ELEMS (O_WFL + 128 * ASTR)
#define O_BIAS (SM_ELEMS * 2)          // bytes: b2[32]f32 then bf[128]f32
#define O_SCR  (O_BIAS + 4 * (32 + 128))
#define SM_BYTES (O_SCR + 8 * 64 * 4)  // + per-warp o1 scratch (slow path)

typedef unsigned u32;

static __device__ __forceinline__ u32 s2u(const void* p) {
    u32 a;
    asm("{ .reg .u64 t; cvta.to.shared.u64 t, %1; cvt.u32.u64 %0, t; }" : "=r"(a) : "l"(p));
    return a;
}
static __device__ __forceinline__ u32 pk(__nv_bfloat16 a, __nv_bfloat16 b) {
    return (u32)__bfloat16_as_ushort(a) | ((u32)__bfloat16_as_ushort(b) << 16);
}
// float2 -> packed bf16x2 hi + packed bf16x2 lo (residual)
static __device__ __forceinline__ void packhl(float a, float b, u32& h, u32& l) {
    __nv_bfloat16 ha = __float2bfloat16(a), hb = __float2bfloat16(b);
    float ra = a - __bfloat162float(ha), rb = b - __bfloat162float(hb);
    h = pk(ha, hb);
    l = pk(__float2bfloat16(ra), __float2bfloat16(rb));
}
static __device__ __forceinline__ void bfsplit(float v, __nv_bfloat16& h, __nv_bfloat16& l) {
    h = __float2bfloat16(v);
    l = __float2bfloat16(v - __bfloat162float(h));
}
static __device__ __forceinline__ void ldmx4(u32 a[4], u32 addr) {
    asm volatile("ldmatrix.sync.aligned.m8n8.x4.shared.b16 {%0,%1,%2,%3}, [%4];"
                 : "=r"(a[0]), "=r"(a[1]), "=r"(a[2]), "=r"(a[3]) : "r"(addr));
}
static __device__ __forceinline__ void mmabf(float c[4], const u32 a[4], u32 b0, u32 b1) {
    asm volatile("mma.sync.aligned.m16n8k16.row.col.f32.bf16.bf16.f32 "
                 "{%0,%1,%2,%3}, {%4,%5,%6,%7}, {%8,%9}, {%0,%1,%2,%3};"
                 : "+f"(c[0]), "+f"(c[1]), "+f"(c[2]), "+f"(c[3])
                 : "r"(a[0]), "r"(a[1]), "r"(a[2]), "r"(a[3]), "r"(b0), "r"(b1));
}

__global__ void __launch_bounds__(NTHREADS, 2)
dynlayer_mma(const float* __restrict__ X,  const float* __restrict__ W1,
             const float* __restrict__ b1, const float* __restrict__ W2,
             const float* __restrict__ b2, const float* __restrict__ Wf,
             const float* __restrict__ bf, float* __restrict__ out, int nrows)
{
    extern __shared__ char smraw[];
    __nv_bfloat16* sh = (__nv_bfloat16*)smraw;
    float* b2s = (float*)(smraw + O_BIAS);
    float* bfs = b2s + 32;
    float* scr = (float*)(smraw + O_SCR);
    const u32 sb = s2u(smraw);
    const int tid = threadIdx.x, wid = tid >> 5, lane = tid & 31;

    // ---- stage weights (bf16 hi/lo, padded row-major) + biases ----
    for (int i = tid; i < 32 * 128; i += NTHREADS) {
        int u = i >> 7, k = i & 127; __nv_bfloat16 h, l; bfsplit(W2[i], h, l);
        sh[O_W2H + u * XSTR + k] = h; sh[O_W2L + u * XSTR + k] = l;
    }
    for (int i = tid; i < 128 * 64; i += NTHREADS) {
        int n = i >> 6, k = i & 63; __nv_bfloat16 h, l; bfsplit(Wf[i], h, l);
        sh[O_WFH + n * ASTR + k] = h; sh[O_WFL + n * ASTR + k] = l;
    }
    if (tid < 32)  b2s[tid] = b2[tid];
    if (tid < 128) bfs[tid] = bf[tid];
    __syncthreads();

    const int q  = lane >> 2;          // row-in-group 0..7
    const int c2 = (lane & 3) * 2;     // k/col pair base

    // ldmatrix B lane-address components (x4: m0..m3 by lane/8)
    const int brow  = ((lane >> 4) & 1) * 8 + (lane & 7);
    const int bcolh = ((lane >> 3) & 1) * 8;
    const u32 w2h = sb + (u32)((O_W2H + brow * XSTR + bcolh) * 2);
    const u32 w2l = sb + (u32)((O_W2L + brow * XSTR + bcolh) * 2);
    const u32 wfh = sb + (u32)((O_WFH + brow * ASTR + bcolh) * 2);
    const u32 wfl = sb + (u32)((O_WFL + brow * ASTR + bcolh) * 2);

    float2 b2c[4];
    #pragma unroll
    for (int nb = 0; nb < 4; nb++)
        b2c[nb] = *reinterpret_cast<const float2*>(b2s + nb * 8 + c2);

    const int ntiles = nrows >> 7;
    for (int t = blockIdx.x; t < ntiles; t += gridDim.x) {
        const long rw = ((long)t << 7) + wid * 16;
        const float* xr0 = X + (rw + q) * 128;
        const float* xr1 = X + (rw + q + 8) * 128;

        // L2 prefetch of next tile's slab (this warp's 16 rows = 8KB)
        if (t + gridDim.x < ntiles) {
            const char* p = (const char*)(X + (rw + (long)gridDim.x * 128) * 128) + lane * 256;
            asm volatile("prefetch.global.L2 [%0];" :: "l"(p));
        }

        float s1 = 0.f, s2 = 0.f;
        float accA[4][4], accB[4][4];
        #pragma unroll
        for (int nb = 0; nb < 4; nb++)
            #pragma unroll
            for (int j = 0; j < 4; j++) { accA[nb][j] = 0.f; accB[nb][j] = 0.f; }

        // ---- GEMM1: o2 = x @ W2^T (M=16,N=32,K=128), A straight from global ----
        #pragma unroll
        for (int half = 0; half < 2; half++) {
            float2 xf[4][4];
            #pragma unroll
            for (int kb = 0; kb < 4; kb++) {          // batch 16 LDG.64 (coalesced sectors)
                const int col0 = (half * 4 + kb) * 16 + c2;
                xf[kb][0] = *reinterpret_cast<const float2*>(xr0 + col0);
                xf[kb][1] = *reinterpret_cast<const float2*>(xr1 + col0);
                xf[kb][2] = *reinterpret_cast<const float2*>(xr0 + col0 + 8);
                xf[kb][3] = *reinterpret_cast<const float2*>(xr1 + col0 + 8);
            }
            #pragma unroll
            for (int kb = 0; kb < 4; kb++) {
                s1 += fabsf(xf[kb][0].x) + fabsf(xf[kb][0].y) + fabsf(xf[kb][2].x) + fabsf(xf[kb][2].y);
                s2 += fabsf(xf[kb][1].x) + fabsf(xf[kb][1].y) + fabsf(xf[kb][3].x) + fabsf(xf[kb][3].y);
            }
            #pragma unroll
            for (int kb = 0; kb < 4; kb++) {
                u32 ah[4], al[4];
                #pragma unroll
                for (int j = 0; j < 4; j++) packhl(xf[kb][j].x, xf[kb][j].y, ah[j], al[j]);
                const int kg = half * 4 + kb;
                #pragma unroll
                for (int nbp = 0; nbp < 2; nbp++) {
                    const u32 off = (u32)((nbp * 16 * XSTR + kg * 16) * 2);
                    u32 bh[4], bl[4];
                    ldmx4(bh, w2h + off);
                    ldmx4(bl, w2l + off);
                    mmabf(accA[2*nbp],   ah, bh[0], bh[1]);   // hh
                    mmabf(accB[2*nbp],   ah, bl[0], bl[1]);   // hl
                    mmabf(accB[2*nbp],   al, bh[0], bh[1]);   // lh
                    mmabf(accA[2*nbp+1], ah, bh[2], bh[3]);
                    mmabf(accB[2*nbp+1], ah, bl[2], bl[3]);
                    mmabf(accB[2*nbp+1], al, bh[2], bh[3]);
                }
            }
        }

        // ---- mask: quad-reduce per-row sum|x| ----
        s1 += __shfl_xor_sync(0xffffffffu, s1, 1); s1 += __shfl_xor_sync(0xffffffffu, s1, 2);
        s2 += __shfl_xor_sync(0xffffffffu, s2, 1); s2 += __shfl_xor_sync(0xffffffffu, s2, 2);
        const bool mr1 = s1 > 128.0f, mr2 = s2 > 128.0f;      // sum>128 <=> mean|x|>1
        const u32 bal1 = __ballot_sync(0xffffffffu, mr1);
        const u32 bal2 = __ballot_sync(0xffffffffu, mr2);

        // ---- epilogue1 in regs: bias+relu, re-split -> GEMM2 A-fragments ----
        u32 A2h[2][4], A2l[2][4];
        #pragma unroll
        for (int nb = 0; nb < 4; nb++) {
            float v0 = fmaxf(accA[nb][0] + accB[nb][0] + b2c[nb].x, 0.f);
            float v1 = fmaxf(accA[nb][1] + accB[nb][1] + b2c[nb].y, 0.f);
            float v2 = fmaxf(accA[nb][2] + accB[nb][2] + b2c[nb].x, 0.f);
            float v3 = fmaxf(accA[nb][3] + accB[nb][3] + b2c[nb].y, 0.f);
            const int kb2 = nb >> 1, base = (nb & 1) * 2;     // C layout == A layout
            packhl(v0, v1, A2h[kb2][base + 0], A2l[kb2][base + 0]);
            packhl(v2, v3, A2h[kb2][base + 1], A2l[kb2][base + 1]);
        }

        // ---- GEMM2: out = o2 @ Wf^T (M=16,N=128,K=32), two N-halves ----
        const long row1 = rw + q, row2 = rw + q + 8;
        #pragma unroll
        for (int nh = 0; nh < 2; nh++) {
            float acc2[8][4];
            #pragma unroll
            for (int nb = 0; nb < 8; nb++)
                #pragma unroll
                for (int j = 0; j < 4; j++) acc2[nb][j] = 0.f;
            #pragma unroll
            for (int kb2 = 0; kb2 < 2; kb2++)
                #pragma unroll
                for (int nbp = 0; nbp < 4; nbp++) {
                    const u32 off = (u32)(((nh * 64 + nbp * 16) * ASTR + kb2 * 16) * 2);
                    u32 bh[4], bl[4];
                    ldmx4(bh, wfh + off);
                    ldmx4(bl, wfl + off);
                    mmabf(acc2[2*nbp],   A2h[kb2], bh[0], bh[1]);
                    mmabf(acc2[2*nbp],   A2h[kb2], bl[0], bl[1]);
                    mmabf(acc2[2*nbp],   A2l[kb2], bh[0], bh[1]);
                    mmabf(acc2[2*nbp+1], A2h[kb2], bh[2], bh[3]);
                    mmabf(acc2[2*nbp+1], A2h[kb2], bl[2], bl[3]);
                    mmabf(acc2[2*nbp+1], A2l[kb2], bh[2], bh[3]);
                }
            #pragma unroll
            for (int nb = 0; nb < 8; nb++) {
                const int col = nh * 64 + nb * 8 + c2;
                const float2 bv = *reinterpret_cast<const float2*>(bfs + col);
                if (!mr1)
                    *reinterpret_cast<float2*>(out + row1 * 128 + col) =
                        make_float2(acc2[nb][0] + bv.x, acc2[nb][1] + bv.y);
                if (!mr2)
                    *reinterpret_cast<float2*>(out + row2 * 128 + col) =
                        make_float2(acc2[nb][2] + bv.x, acc2[nb][3] + bv.y);
            }
        }

        // ---- rare slow path: masked rows computed fully in fp32 ----
        if (bal1 | bal2) {
            float* o1s = scr + wid * 64;
            for (int r = 0; r < 16; r++) {
                const bool masked = (r < 8) ? ((bal1 >> (4 * r)) & 1u)
                                            : ((bal2 >> (4 * (r - 8))) & 1u);
                if (!masked) continue;
                const float4* xg4 = reinterpret_cast<const float4*>(X + (rw + r) * 128);
                #pragma unroll
                for (int uu = 0; uu < 2; uu++) {
                    const int u = lane + uu * 32;
                    const float4* wr = reinterpret_cast<const float4*>(W1 + u * 128);
                    float s = 0.f;
                    for (int k = 0; k < 32; k++) {
                        float4 a = xg4[k], w = wr[k];
                        s += a.x * w.x + a.y * w.y + a.z * w.z + a.w * w.w;
                    }
                    o1s[u] = fmaxf(s + b1[u], 0.f);
                }
                __syncwarp();
                #pragma unroll
                for (int jj = 0; jj < 4; jj++) {
                    const int d = lane + jj * 32;
                    const float* wf = Wf + d * 64;
                    float acc = bfs[d];
                    for (int u = 0; u < 64; u++) acc += o1s[u] * wf[u];
                    out[(rw + r) * 128 + d] = acc;
                }
                __syncwarp();
            }
        }
    }
}

extern "C" void kernel_launch(void* const* d_in, const int* in_sizes, int n_in,
                              void* d_out, int out_size)
{
    const float* X  = (const float*)d_in[0];
    const float* W1 = (const float*)d_in[1];
    const float* b1 = (const float*)d_in[2];
    const float* W2 = (const float*)d_in[3];
    const float* b2 = (const float*)d_in[4];
    const float* Wf = (const float*)d_in[5];
    const float* bf = (const float*)d_in[6];
    float* out = (float*)d_out;

    const int nrows = in_sizes[0] / 128;

    cudaFuncSetAttribute(dynlayer_mma,
                         cudaFuncAttributeMaxDynamicSharedMemorySize, SM_BYTES);
    int nsm = 148;
    cudaDeviceGetAttribute(&nsm, cudaDevAttrMultiProcessorCount, 0);

    dynlayer_mma<<<2 * nsm, NTHREADS, SM_BYTES>>>(X, W1, b1, W2, b2, Wf, bf, out, nrows);
}